// round 8
// baseline (speedup 1.0000x reference)
#include <cuda_runtime.h>

// Local covariance: out = boxmean5( (center(x)-boxmean5(x)) * (center(y)-boxmean5(y)) )
// x,y: [16,1,1024,1024] f32 -> out: [16,1,1016,1016] f32
//
// Register-resident streaming, 4 columns per lane (float4), one-row software
// prefetch. R7: grid reshaped to 720 blocks (9 x 5 x 16) with 5-blocks/SM
// register cap so ~20 warps/SM are resident (was 4 blocks/SM, one 3.9-block
// wave). Streaming stores for output.
// No shared memory, no __syncthreads.

#define H  1024
#define W  1024
#define OH 1016
#define OW 1016
#define NB 16

#define CPWARP 120            // valid output cols per warp (128 raw - 8 halo)
#define NCS    9              // ceil(1016/120)
#define ORS    52             // output rows per strip
#define IRS    60             // input rows per strip (= ORS + 8, multiple of 5)
#define NRS    20             // 20*52 = 1040 >= 1016

__global__ __launch_bounds__(128, 5)
void cov_kernel(const float* __restrict__ x,
                const float* __restrict__ y,
                float* __restrict__ out)
{
    const int lane = threadIdx.x & 31;
    const int wrp  = threadIdx.x >> 5;

    const int cs = blockIdx.x;               // column strip 0..8
    const int rs = blockIdx.y * 4 + wrp;     // row strip 0..19
    const int b  = blockIdx.z;

    const int c0 = cs * CPWARP + lane * 4;   // first raw col of lane
    const int r0 = rs * ORS;                 // first input row of strip

    const float* __restrict__ xb = x + (long)b * (H * W);
    const float* __restrict__ yb = y + (long)b * (H * W);
    float*       __restrict__ ob = out + (long)b * (OH * OW);

    const bool colok = (c0 < W);                      // full float4 load valid
    const bool outok = (lane < 30) && (c0 < OW);      // full float4 store valid
    const float inv25 = 1.0f / 25.0f;

    // register ring buffers (constant-indexed in unrolled phase loop)
    float xr[5][4], yr[5][4], hpr[5][4];
    float vsx[4], vsy[4], vhp[4];
    #pragma unroll
    for (int s = 0; s < 5; ++s)
        #pragma unroll
        for (int i = 0; i < 4; ++i) { xr[s][i] = 0.f; yr[s][i] = 0.f; hpr[s][i] = 0.f; }
    #pragma unroll
    for (int i = 0; i < 4; ++i) { vsx[i] = 0.f; vsy[i] = 0.f; vhp[i] = 0.f; }

    const float4* xp = (const float4*)(xb + (long)r0 * W) + (c0 >> 2);
    const float4* yp = (const float4*)(yb + (long)r0 * W) + (c0 >> 2);

    // ---- prefetch row 0 ----
    float4 fx, fy;
    {
        const bool rok = (r0 < H) && colok;
        if (rok) { fx = __ldg(xp); fy = __ldg(yp); }
        else { fx = make_float4(0.f, 0.f, 0.f, 0.f); fy = make_float4(0.f, 0.f, 0.f, 0.f); }
        xp += W / 4; yp += W / 4;
    }

    for (int rr = 0; rr < IRS; rr += 5) {
        #pragma unroll
        for (int ph = 0; ph < 5; ++ph) {
            const int rrp = rr + ph;

            // ---- consume prefetched row rrp; prefetch row rrp+1 ----
            float xa[4] = {fx.x, fx.y, fx.z, fx.w};
            float ya[4] = {fy.x, fy.y, fy.z, fy.w};
            {
                const bool rok = (r0 + rrp + 1) < H && colok;
                if (rok) { fx = __ldg(xp); fy = __ldg(yp); }
                else { fx = make_float4(0.f, 0.f, 0.f, 0.f); fy = make_float4(0.f, 0.f, 0.f, 0.f); }
                xp += W / 4; yp += W / 4;
            }

            // ---- vertical running 5-sums of raw columns ----
            #pragma unroll
            for (int i = 0; i < 4; ++i) {
                vsx[i] += xa[i] - xr[ph][i]; xr[ph][i] = xa[i];
                vsy[i] += ya[i] - yr[ph][i]; yr[ph][i] = ya[i];
            }

            // ---- horizontal 5-sums of vertical sums -> 5x5 box sums ----
            float nx[4], ny[4];
            #pragma unroll
            for (int i = 0; i < 4; ++i) {
                nx[i] = __shfl_down_sync(0xffffffffu, vsx[i], 1);
                ny[i] = __shfl_down_sync(0xffffffffu, vsy[i], 1);
            }
            float bx[4], by[4];
            {
                float t = (vsx[0] + vsx[1]) + (vsx[2] + vsx[3]);
                bx[0] = t + nx[0];
                bx[1] = bx[0] - vsx[0] + nx[1];
                bx[2] = bx[1] - vsx[1] + nx[2];
                bx[3] = bx[2] - vsx[2] + nx[3];
                t = (vsy[0] + vsy[1]) + (vsy[2] + vsy[3]);
                by[0] = t + ny[0];
                by[1] = by[0] - vsy[0] + ny[1];
                by[2] = by[1] - vsy[1] + ny[2];
                by[3] = by[2] - vsy[2] + ny[3];
            }

            // ---- center pixels: row rrp-2 (ring slot (ph+3)%5), col u+2 ----
            const int s = (ph + 3) % 5;
            float cx[4], cy[4];
            cx[0] = xr[s][2]; cx[1] = xr[s][3];
            cx[2] = __shfl_down_sync(0xffffffffu, xr[s][0], 1);
            cx[3] = __shfl_down_sync(0xffffffffu, xr[s][1], 1);
            cy[0] = yr[s][2]; cy[1] = yr[s][3];
            cy[2] = __shfl_down_sync(0xffffffffu, yr[s][0], 1);
            cy[3] = __shfl_down_sync(0xffffffffu, yr[s][1], 1);

            float pc[4];
            #pragma unroll
            for (int i = 0; i < 4; ++i)
                pc[i] = (cx[i] - bx[i] * inv25) * (cy[i] - by[i] * inv25);

            // ---- horizontal 5-sum of p ----
            float np[4];
            #pragma unroll
            for (int i = 0; i < 4; ++i)
                np[i] = __shfl_down_sync(0xffffffffu, pc[i], 1);

            float hp0, hp1, hp2, hp3;
            {
                float t = (pc[0] + pc[1]) + (pc[2] + pc[3]);
                hp0 = t + np[0];
                hp1 = hp0 - pc[0] + np[1];
                hp2 = hp1 - pc[1] + np[2];
                hp3 = hp2 - pc[2] + np[3];
            }
            if (rrp < 4) { hp0 = 0.f; hp1 = 0.f; hp2 = 0.f; hp3 = 0.f; }

            // ---- vertical running 5-sum of hp -> output row r0+rrp-8 ----
            vhp[0] += hp0 - hpr[ph][0]; hpr[ph][0] = hp0;
            vhp[1] += hp1 - hpr[ph][1]; hpr[ph][1] = hp1;
            vhp[2] += hp2 - hpr[ph][2]; hpr[ph][2] = hp2;
            vhp[3] += hp3 - hpr[ph][3]; hpr[ph][3] = hp3;

            if (rrp >= 8) {
                const int orow = r0 + rrp - 8;
                if (outok && orow < OH) {
                    float4 o = make_float4(vhp[0] * inv25, vhp[1] * inv25,
                                           vhp[2] * inv25, vhp[3] * inv25);
                    __stcs((float4*)(ob + (long)orow * OW + c0), o);
                }
            }
        }
    }
}

extern "C" void kernel_launch(void* const* d_in, const int* in_sizes, int n_in,
                              void* d_out, int out_size)
{
    (void)in_sizes; (void)n_in; (void)out_size;
    const float* x = (const float*)d_in[0];
    const float* y = (const float*)d_in[1];
    float* out = (float*)d_out;

    dim3 grid(NCS, NRS / 4, NB);   // 9 col strips x 20 row strips x 16 images
    cov_kernel<<<grid, 128>>>(x, y, out);
}

// round 9
// speedup vs baseline: 1.0422x; 1.0422x over previous
#include <cuda_runtime.h>

// Local covariance: out = boxmean5( (center(x)-boxmean5(x)) * (center(y)-boxmean5(y)) )
// x,y: [16,1,1024,1024] f32 -> out: [16,1,1016,1016] f32
//
// Register-resident streaming, 4 cols/lane (float4). R9: 2-row-deep software
// prefetch via two alternating register buffers (even/odd phases of a 10-way
// unrolled phase loop), 3 blocks/SM so regs are plentiful (no spills) and each
// warp keeps 4 LDG.128 in flight. Streaming stores for output.
// No shared memory, no __syncthreads.

#define H  1024
#define W  1024
#define OH 1016
#define OW 1016
#define NB 16

#define CPWARP 120            // valid output cols per warp (128 raw - 8 halo)
#define NCS    9              // ceil(1016/120)
#define ORS    92             // output rows per warp strip
#define IRS    100            // input rows per strip (= ORS + 8, multiple of 10)
#define NRS    12             // 12*92 = 1104 >= 1016

__global__ __launch_bounds__(128, 3)
void cov_kernel(const float* __restrict__ x,
                const float* __restrict__ y,
                float* __restrict__ out)
{
    const int lane = threadIdx.x & 31;
    const int wrp  = threadIdx.x >> 5;

    const int cs = blockIdx.x;               // column strip 0..8
    const int rs = blockIdx.y * 4 + wrp;     // row strip 0..11
    const int b  = blockIdx.z;

    const int c0 = cs * CPWARP + lane * 4;   // first raw col of lane
    const int r0 = rs * ORS;                 // first input row of strip

    const float* __restrict__ xb = x + (long)b * (H * W);
    const float* __restrict__ yb = y + (long)b * (H * W);
    float*       __restrict__ ob = out + (long)b * (OH * OW);

    const bool colok = (c0 < W);                      // full float4 load valid
    const bool outok = (lane < 30) && (c0 < OW);      // full float4 store valid
    const float inv25 = 1.0f / 25.0f;

    // register ring buffers (constant-indexed in unrolled phase loop)
    float xr[5][4], yr[5][4], hpr[5][4];
    float vsx[4], vsy[4], vhp[4];
    #pragma unroll
    for (int s = 0; s < 5; ++s)
        #pragma unroll
        for (int i = 0; i < 4; ++i) { xr[s][i] = 0.f; yr[s][i] = 0.f; hpr[s][i] = 0.f; }
    #pragma unroll
    for (int i = 0; i < 4; ++i) { vsx[i] = 0.f; vsy[i] = 0.f; vhp[i] = 0.f; }

    const float4* xp = (const float4*)(xb + (long)r0 * W) + (c0 >> 2);
    const float4* yp = (const float4*)(yb + (long)r0 * W) + (c0 >> 2);

    const float4 z4 = make_float4(0.f, 0.f, 0.f, 0.f);

    // ---- prefetch rows r0 (buffer A) and r0+1 (buffer B) ----
    float4 fxA, fyA, fxB, fyB;
    {
        bool okA = (r0 < H) && colok;
        bool okB = (r0 + 1 < H) && colok;
        fxA = okA ? __ldg(xp)         : z4;
        fyA = okA ? __ldg(yp)         : z4;
        fxB = okB ? __ldg(xp + W / 4) : z4;
        fyB = okB ? __ldg(yp + W / 4) : z4;
        xp += W / 2; yp += W / 2;     // next A-load target: row r0+2
    }

    for (int rr = 0; rr < IRS; rr += 10) {
        #pragma unroll
        for (int ph = 0; ph < 10; ++ph) {
            const int rrp = rr + ph;
            const int sl  = ph % 5;            // ring slot of current row
            const int sc  = (ph + 3) % 5;      // ring slot of row rrp-2 (center)

            // ---- consume buffer (A on even phase, B on odd); refill with row rrp+2 ----
            float xa[4], ya[4];
            {
                const bool rok = (r0 + rrp + 2) < H && colok;
                if ((ph & 1) == 0) {
                    xa[0] = fxA.x; xa[1] = fxA.y; xa[2] = fxA.z; xa[3] = fxA.w;
                    ya[0] = fyA.x; ya[1] = fyA.y; ya[2] = fyA.z; ya[3] = fyA.w;
                    fxA = rok ? __ldg(xp) : z4;
                    fyA = rok ? __ldg(yp) : z4;
                } else {
                    xa[0] = fxB.x; xa[1] = fxB.y; xa[2] = fxB.z; xa[3] = fxB.w;
                    ya[0] = fyB.x; ya[1] = fyB.y; ya[2] = fyB.z; ya[3] = fyB.w;
                    fxB = rok ? __ldg(xp) : z4;
                    fyB = rok ? __ldg(yp) : z4;
                }
                xp += W / 4; yp += W / 4;
            }

            // ---- vertical running 5-sums of raw columns ----
            #pragma unroll
            for (int i = 0; i < 4; ++i) {
                vsx[i] += xa[i] - xr[sl][i]; xr[sl][i] = xa[i];
                vsy[i] += ya[i] - yr[sl][i]; yr[sl][i] = ya[i];
            }

            // ---- horizontal 5-sums of vertical sums -> 5x5 box sums ----
            float nx[4], ny[4];
            #pragma unroll
            for (int i = 0; i < 4; ++i) {
                nx[i] = __shfl_down_sync(0xffffffffu, vsx[i], 1);
                ny[i] = __shfl_down_sync(0xffffffffu, vsy[i], 1);
            }
            float bx[4], by[4];
            {
                float t = (vsx[0] + vsx[1]) + (vsx[2] + vsx[3]);
                bx[0] = t + nx[0];
                bx[1] = bx[0] - vsx[0] + nx[1];
                bx[2] = bx[1] - vsx[1] + nx[2];
                bx[3] = bx[2] - vsx[2] + nx[3];
                t = (vsy[0] + vsy[1]) + (vsy[2] + vsy[3]);
                by[0] = t + ny[0];
                by[1] = by[0] - vsy[0] + ny[1];
                by[2] = by[1] - vsy[1] + ny[2];
                by[3] = by[2] - vsy[2] + ny[3];
            }

            // ---- center pixels: row rrp-2 (ring slot sc), col u+2 ----
            float cx[4], cy[4];
            cx[0] = xr[sc][2]; cx[1] = xr[sc][3];
            cx[2] = __shfl_down_sync(0xffffffffu, xr[sc][0], 1);
            cx[3] = __shfl_down_sync(0xffffffffu, xr[sc][1], 1);
            cy[0] = yr[sc][2]; cy[1] = yr[sc][3];
            cy[2] = __shfl_down_sync(0xffffffffu, yr[sc][0], 1);
            cy[3] = __shfl_down_sync(0xffffffffu, yr[sc][1], 1);

            float pc[4];
            #pragma unroll
            for (int i = 0; i < 4; ++i)
                pc[i] = (cx[i] - bx[i] * inv25) * (cy[i] - by[i] * inv25);

            // ---- horizontal 5-sum of p ----
            float np[4];
            #pragma unroll
            for (int i = 0; i < 4; ++i)
                np[i] = __shfl_down_sync(0xffffffffu, pc[i], 1);

            float hp0, hp1, hp2, hp3;
            {
                float t = (pc[0] + pc[1]) + (pc[2] + pc[3]);
                hp0 = t + np[0];
                hp1 = hp0 - pc[0] + np[1];
                hp2 = hp1 - pc[1] + np[2];
                hp3 = hp2 - pc[2] + np[3];
            }
            if (rrp < 4) { hp0 = 0.f; hp1 = 0.f; hp2 = 0.f; hp3 = 0.f; }

            // ---- vertical running 5-sum of hp -> output row r0+rrp-8 ----
            vhp[0] += hp0 - hpr[sl][0]; hpr[sl][0] = hp0;
            vhp[1] += hp1 - hpr[sl][1]; hpr[sl][1] = hp1;
            vhp[2] += hp2 - hpr[sl][2]; hpr[sl][2] = hp2;
            vhp[3] += hp3 - hpr[sl][3]; hpr[sl][3] = hp3;

            if (rrp >= 8) {
                const int orow = r0 + rrp - 8;
                if (outok && orow < OH) {
                    float4 o = make_float4(vhp[0] * inv25, vhp[1] * inv25,
                                           vhp[2] * inv25, vhp[3] * inv25);
                    __stcs((float4*)(ob + (long)orow * OW + c0), o);
                }
            }
        }
    }
}

extern "C" void kernel_launch(void* const* d_in, const int* in_sizes, int n_in,
                              void* d_out, int out_size)
{
    (void)in_sizes; (void)n_in; (void)out_size;
    const float* x = (const float*)d_in[0];
    const float* y = (const float*)d_in[1];
    float* out = (float*)d_out;

    dim3 grid(NCS, NRS / 4, NB);   // 9 col strips x 12 row strips x 16 images
    cov_kernel<<<grid, 128>>>(x, y, out);
}

// round 11
// speedup vs baseline: 1.4129x; 1.3556x over previous
#include <cuda_runtime.h>
#include <cstdint>

// Local covariance: out = boxmean5( (center(x)-boxmean5(x)) * (center(y)-boxmean5(y)) )
// x,y: [16,1,1024,1024] f32 -> out: [16,1,1016,1016] f32
//
// R10: R6 compute core (register rings + shuffles, 4 cols/lane) with a
// per-warp cp.async (LDGSTS) pipeline, depth 8 rows, staged in SMEM.
// Each lane copies/reads only its own 16B x / 16B y per stage -> per-thread
// async groups, no barriers. Zero register cost for pipeline depth.

#define H  1024
#define W  1024
#define OH 1016
#define OW 1016
#define NB 16

#define CPWARP 120            // valid output cols per warp (128 raw - 8 halo)
#define NCS    9              // ceil(1016/120)
#define ORS    67             // output rows per strip
#define IRS    75             // input rows per strip (= ORS + 8, multiple of 5)
#define NRS    16             // 16*67 = 1072 >= 1016
#define DEPTH  8              // cp.async pipeline depth (rows in flight)

__device__ __forceinline__ void cp16(uint32_t dst, const void* src, uint32_t zf)
{
    // 16-byte async copy; zf==0 -> zero-fill (no global read)
    asm volatile("cp.async.cg.shared.global [%0], [%1], 16, %2;\n"
                 :: "r"(dst), "l"(src), "r"(zf) : "memory");
}

__global__ __launch_bounds__(128, 4)
void cov_kernel(const float* __restrict__ x,
                const float* __restrict__ y,
                float* __restrict__ out)
{
    // per-warp ring: DEPTH stages x (32 lanes x 16B x) + (32 lanes x 16B y) = 1KB/stage
    __shared__ __align__(16) float4 ring[4][DEPTH][64];

    const int lane = threadIdx.x & 31;
    const int wrp  = threadIdx.x >> 5;

    const int cs = blockIdx.x;               // column strip 0..8
    const int rs = blockIdx.y * 4 + wrp;     // row strip 0..15
    const int b  = blockIdx.z;

    const int c0 = cs * CPWARP + lane * 4;   // first raw col of lane
    const int r0 = rs * ORS;                 // first input row of strip

    const float* __restrict__ xb = x + (long)b * (H * W);
    const float* __restrict__ yb = y + (long)b * (H * W);
    float*       __restrict__ ob = out + (long)b * (OH * OW);

    const bool colok = (c0 < W);
    const int  cc    = colok ? c0 : 0;                // clamped col for address safety
    const bool outok = (lane < 30) && (c0 < OW);
    const float inv25 = 1.0f / 25.0f;

    const uint32_t sb  = (uint32_t)__cvta_generic_to_shared(&ring[wrp][0][0]);
    const uint32_t sll = lane * 16;

    // ---- prime pipeline: rows r0 .. r0+DEPTH-1 into stages 0..DEPTH-1 ----
    #pragma unroll
    for (int d = 0; d < DEPTH; ++d) {
        const int row = r0 + d;
        const int rL  = row < H ? row : (H - 1);
        const uint32_t zf = (row < H && colok) ? 16u : 0u;
        const uint32_t dst = sb + ((uint32_t)d << 10) + sll;
        cp16(dst,       xb + (long)rL * W + cc, zf);
        cp16(dst + 512, yb + (long)rL * W + cc, zf);
        asm volatile("cp.async.commit_group;" ::: "memory");
    }

    // register ring buffers (constant-indexed in unrolled phase loop)
    float xr[5][4], yr[5][4], hpr[5][4];
    float vsx[4], vsy[4], vhp[4];
    #pragma unroll
    for (int s = 0; s < 5; ++s)
        #pragma unroll
        for (int i = 0; i < 4; ++i) { xr[s][i] = 0.f; yr[s][i] = 0.f; hpr[s][i] = 0.f; }
    #pragma unroll
    for (int i = 0; i < 4; ++i) { vsx[i] = 0.f; vsy[i] = 0.f; vhp[i] = 0.f; }

    for (int rr = 0; rr < IRS; rr += 5) {
        #pragma unroll
        for (int ph = 0; ph < 5; ++ph) {
            const int rrp = rr + ph;
            const int st  = rrp & (DEPTH - 1);

            // ---- wait for row rrp's copies (own lane's only), consume ----
            asm volatile("cp.async.wait_group 7;" ::: "memory");
            float4 xv = ring[wrp][st][lane];
            float4 yv = ring[wrp][st][32 + lane];

            float xa[4] = {xv.x, xv.y, xv.z, xv.w};
            float ya[4] = {yv.x, yv.y, yv.z, yv.w};

            // ---- vertical running 5-sums of raw columns (consumes LDS data) ----
            #pragma unroll
            for (int i = 0; i < 4; ++i) {
                vsx[i] += xa[i] - xr[ph][i]; xr[ph][i] = xa[i];
                vsy[i] += ya[i] - yr[ph][i]; yr[ph][i] = ya[i];
            }

            // ---- refill same stage with row rrp+DEPTH ----
            {
                const int row = r0 + rrp + DEPTH;
                const int rL  = row < H ? row : (H - 1);
                const uint32_t zf = ((rrp + DEPTH) < IRS && row < H && colok) ? 16u : 0u;
                const uint32_t dst = sb + ((uint32_t)st << 10) + sll;
                cp16(dst,       xb + (long)rL * W + cc, zf);
                cp16(dst + 512, yb + (long)rL * W + cc, zf);
                asm volatile("cp.async.commit_group;" ::: "memory");
            }

            // ---- horizontal 5-sums of vertical sums -> 5x5 box sums ----
            float nx[4], ny[4];
            #pragma unroll
            for (int i = 0; i < 4; ++i) {
                nx[i] = __shfl_down_sync(0xffffffffu, vsx[i], 1);
                ny[i] = __shfl_down_sync(0xffffffffu, vsy[i], 1);
            }
            float bx[4], by[4];
            {
                float t = (vsx[0] + vsx[1]) + (vsx[2] + vsx[3]);
                bx[0] = t + nx[0];
                bx[1] = bx[0] - vsx[0] + nx[1];
                bx[2] = bx[1] - vsx[1] + nx[2];
                bx[3] = bx[2] - vsx[2] + nx[3];
                t = (vsy[0] + vsy[1]) + (vsy[2] + vsy[3]);
                by[0] = t + ny[0];
                by[1] = by[0] - vsy[0] + ny[1];
                by[2] = by[1] - vsy[1] + ny[2];
                by[3] = by[2] - vsy[2] + ny[3];
            }

            // ---- center pixels: row rrp-2 (ring slot (ph+3)%5), col u+2 ----
            const int s = (ph + 3) % 5;
            float cx[4], cy[4];
            cx[0] = xr[s][2]; cx[1] = xr[s][3];
            cx[2] = __shfl_down_sync(0xffffffffu, xr[s][0], 1);
            cx[3] = __shfl_down_sync(0xffffffffu, xr[s][1], 1);
            cy[0] = yr[s][2]; cy[1] = yr[s][3];
            cy[2] = __shfl_down_sync(0xffffffffu, yr[s][0], 1);
            cy[3] = __shfl_down_sync(0xffffffffu, yr[s][1], 1);

            float pc[4];
            #pragma unroll
            for (int i = 0; i < 4; ++i)
                pc[i] = (cx[i] - bx[i] * inv25) * (cy[i] - by[i] * inv25);

            // ---- horizontal 5-sum of p ----
            float np[4];
            #pragma unroll
            for (int i = 0; i < 4; ++i)
                np[i] = __shfl_down_sync(0xffffffffu, pc[i], 1);

            float hp0, hp1, hp2, hp3;
            {
                float t = (pc[0] + pc[1]) + (pc[2] + pc[3]);
                hp0 = t + np[0];
                hp1 = hp0 - pc[0] + np[1];
                hp2 = hp1 - pc[1] + np[2];
                hp3 = hp2 - pc[2] + np[3];
            }
            if (rrp < 4) { hp0 = 0.f; hp1 = 0.f; hp2 = 0.f; hp3 = 0.f; }

            // ---- vertical running 5-sum of hp -> output row r0+rrp-8 ----
            vhp[0] += hp0 - hpr[ph][0]; hpr[ph][0] = hp0;
            vhp[1] += hp1 - hpr[ph][1]; hpr[ph][1] = hp1;
            vhp[2] += hp2 - hpr[ph][2]; hpr[ph][2] = hp2;
            vhp[3] += hp3 - hpr[ph][3]; hpr[ph][3] = hp3;

            if (rrp >= 8) {
                const int orow = r0 + rrp - 8;
                if (outok && orow < OH) {
                    float4 o = make_float4(vhp[0] * inv25, vhp[1] * inv25,
                                           vhp[2] * inv25, vhp[3] * inv25);
                    __stcs((float4*)(ob + (long)orow * OW + c0), o);
                }
            }
        }
    }
}

extern "C" void kernel_launch(void* const* d_in, const int* in_sizes, int n_in,
                              void* d_out, int out_size)
{
    (void)in_sizes; (void)n_in; (void)out_size;
    const float* x = (const float*)d_in[0];
    const float* y = (const float*)d_in[1];
    float* out = (float*)d_out;

    dim3 grid(NCS, NRS / 4, NB);   // 9 col strips x 16 row strips x 16 images
    cov_kernel<<<grid, 128>>>(x, y, out);
}